// round 1
// baseline (speedup 1.0000x reference)
#include <cuda_runtime.h>
#include <cuda_bf16.h>
#include <math.h>

// Problem constants (fixed by setup_inputs)
#define NMAX 50000
#define D 128
#define NUM_INNER 2   // number_of_layers = 4 -> 2 inner LEConv layers

// ---------------- scratch (device globals; no allocation allowed) -------------
__device__ float g_H[NMAX * D];     // activations (layer input)
__device__ float g_A[NMAX * D];     // lin1(x) (+b1)  -> gathered by edges
__device__ float g_B[NMAX * D];     // lin2(x)
__device__ float g_C[NMAX * D];     // lin3(x) (+b3)
__device__ float g_AGG[NMAX * D];   // edge-scatter accumulator
__device__ float g_wsum[NMAX];      // sum of edge weights per dst
__device__ float g_aO[NMAX];        // final-layer lin1 scalar per node
__device__ float g_colsum[D];
__device__ float g_colsumsq[D];
__device__ float g_colmean[D];
__device__ float g_colinv[D];

// ---------------- utility kernels -------------------------------------------
__global__ void zero_f4(float4* p, int n4) {
    int i = blockIdx.x * blockDim.x + threadIdx.x;
    if (i < n4) p[i] = make_float4(0.f, 0.f, 0.f, 0.f);
}
__global__ void zero_f(float* p, int n) {
    int i = blockIdx.x * blockDim.x + threadIdx.x;
    if (i < n) p[i] = 0.f;
}

// per-column sum / sumsq over N rows (128 threads = 128 columns)
__global__ void colstats_kernel(const float* __restrict__ x, int N) {
    int c = threadIdx.x;
    float s = 0.f, ss = 0.f;
    for (int r = blockIdx.x; r < N; r += gridDim.x) {
        float v = x[(size_t)r * D + c];
        s += v;
        ss += v * v;
    }
    atomicAdd(&g_colsum[c], s);
    atomicAdd(&g_colsumsq[c], ss);
}

// finalize mean / 1/(std+1e-6) (std unbiased, ddof=1)
__global__ void colfinal_kernel(int N) {
    int c = threadIdx.x;
    float mean = g_colsum[c] / (float)N;
    float var = (g_colsumsq[c] - (float)N * mean * mean) / (float)(N - 1);
    var = fmaxf(var, 0.f);
    g_colmean[c] = mean;
    g_colinv[c] = 1.f / (sqrtf(var) + 1e-6f);
}

// x -> standardized H
__global__ void normalize_kernel(const float4* __restrict__ x4, float4* __restrict__ h4, int n4) {
    int i = blockIdx.x * blockDim.x + threadIdx.x;
    if (i >= n4) return;
    int c = (i & 31) * 4;
    float4 v = x4[i];
    v.x = (v.x - g_colmean[c + 0]) * g_colinv[c + 0];
    v.y = (v.y - g_colmean[c + 1]) * g_colinv[c + 1];
    v.z = (v.z - g_colmean[c + 2]) * g_colinv[c + 2];
    v.w = (v.w - g_colmean[c + 3]) * g_colinv[c + 3];
    h4[i] = v;
}

// wsum[dst] += w  (once; layer-invariant)
__global__ void wsum_kernel(const int* __restrict__ dst, const float* __restrict__ w, int E) {
    int e = blockIdx.x * blockDim.x + threadIdx.x;
    if (e < E) atomicAdd(&g_wsum[dst[e]], w[e]);
}

// ---------------- SGEMM: Out[M,128] = X[M,128] @ W[128,128] (+ bias) ---------
#define BM 128
#define BN 128
#define BK 8
#define TM 8
#define TN 8

__global__ __launch_bounds__(256) void sgemm128(
    const float* __restrict__ X, const float* __restrict__ W,
    const float* __restrict__ bias, float* __restrict__ Out, int M)
{
    __shared__ float As[BK][BM];
    __shared__ float Bs[BK][BN];
    int tid = threadIdx.x;
    int tx = tid & 15;        // col group (0..15)
    int ty = tid >> 4;        // row group (0..15)
    int m0 = blockIdx.x * BM;

    int aRow = tid >> 1;            // 0..127
    int aK = (tid & 1) * 4;         // 0 or 4
    int bK = tid >> 5;              // 0..7
    int bN = (tid & 31) * 4;        // 0..124

    float acc[TM][TN];
#pragma unroll
    for (int i = 0; i < TM; i++)
#pragma unroll
        for (int j = 0; j < TN; j++) acc[i][j] = 0.f;

    for (int k0 = 0; k0 < D; k0 += BK) {
        float4 av = make_float4(0.f, 0.f, 0.f, 0.f);
        int gr = m0 + aRow;
        if (gr < M) av = *reinterpret_cast<const float4*>(X + (size_t)gr * D + k0 + aK);
        As[aK + 0][aRow] = av.x;
        As[aK + 1][aRow] = av.y;
        As[aK + 2][aRow] = av.z;
        As[aK + 3][aRow] = av.w;
        *reinterpret_cast<float4*>(&Bs[bK][bN]) =
            *reinterpret_cast<const float4*>(W + (size_t)(k0 + bK) * D + bN);
        __syncthreads();
#pragma unroll
        for (int k = 0; k < BK; k++) {
            float ra[TM], rb[TN];
            float4 a0 = *reinterpret_cast<const float4*>(&As[k][ty * TM]);
            float4 a1 = *reinterpret_cast<const float4*>(&As[k][ty * TM + 4]);
            ra[0] = a0.x; ra[1] = a0.y; ra[2] = a0.z; ra[3] = a0.w;
            ra[4] = a1.x; ra[5] = a1.y; ra[6] = a1.z; ra[7] = a1.w;
            float4 b0 = *reinterpret_cast<const float4*>(&Bs[k][tx * TN]);
            float4 b1 = *reinterpret_cast<const float4*>(&Bs[k][tx * TN + 4]);
            rb[0] = b0.x; rb[1] = b0.y; rb[2] = b0.z; rb[3] = b0.w;
            rb[4] = b1.x; rb[5] = b1.y; rb[6] = b1.z; rb[7] = b1.w;
#pragma unroll
            for (int i = 0; i < TM; i++)
#pragma unroll
                for (int j = 0; j < TN; j++) acc[i][j] = fmaf(ra[i], rb[j], acc[i][j]);
        }
        __syncthreads();
    }

#pragma unroll
    for (int i = 0; i < TM; i++) {
        int gm = m0 + ty * TM + i;
        if (gm >= M) continue;
#pragma unroll
        for (int j = 0; j < TN; j += 4) {
            int gn = tx * TN + j;
            float4 v = make_float4(acc[i][j], acc[i][j + 1], acc[i][j + 2], acc[i][j + 3]);
            if (bias) {
                v.x += bias[gn + 0];
                v.y += bias[gn + 1];
                v.z += bias[gn + 2];
                v.w += bias[gn + 3];
            }
            *reinterpret_cast<float4*>(Out + (size_t)gm * D + gn) = v;
        }
    }
}

// ---------------- edge scatter: AGG[dst] += w * A[src]  (warp per edge) ------
__global__ void scatter_kernel(const float* __restrict__ A, const int* __restrict__ src,
                               const int* __restrict__ dst, const float* __restrict__ w,
                               float* __restrict__ AGG, int E)
{
    int warpId = (blockIdx.x * blockDim.x + threadIdx.x) >> 5;
    int lane = threadIdx.x & 31;
    if (warpId >= E) return;
    int s = src[warpId];
    int d = dst[warpId];
    float wv = w[warpId];
    float4 v = *reinterpret_cast<const float4*>(A + (size_t)s * D + lane * 4);
    float* o = AGG + (size_t)d * D + lane * 4;
    atomicAdd(o + 0, wv * v.x);
    atomicAdd(o + 1, wv * v.y);
    atomicAdd(o + 2, wv * v.z);
    atomicAdd(o + 3, wv * v.w);
}

// ---------------- combine + LayerNorm + LeakyReLU (warp per row) -------------
__global__ void combine_ln_kernel(const float* __restrict__ AGG, const float* __restrict__ Bm,
                                  const float* __restrict__ Cm, const float* __restrict__ g,
                                  const float* __restrict__ beta, float* __restrict__ H, int N)
{
    int row = (blockIdx.x * blockDim.x + threadIdx.x) >> 5;
    int lane = threadIdx.x & 31;
    if (row >= N) return;
    float ws = g_wsum[row];
    size_t base = (size_t)row * D + lane * 4;
    float4 a = *reinterpret_cast<const float4*>(AGG + base);
    float4 b = *reinterpret_cast<const float4*>(Bm + base);
    float4 c = *reinterpret_cast<const float4*>(Cm + base);
    float v0 = a.x - ws * b.x + c.x;
    float v1 = a.y - ws * b.y + c.y;
    float v2 = a.z - ws * b.z + c.z;
    float v3 = a.w - ws * b.w + c.w;
    float s = v0 + v1 + v2 + v3;
    float ss = v0 * v0 + v1 * v1 + v2 * v2 + v3 * v3;
#pragma unroll
    for (int o = 16; o; o >>= 1) {
        s += __shfl_xor_sync(0xFFFFFFFFu, s, o);
        ss += __shfl_xor_sync(0xFFFFFFFFu, ss, o);
    }
    float mean = s * (1.f / (float)D);
    float var = ss * (1.f / (float)D) - mean * mean;
    float inv = rsqrtf(var + 1e-5f);
    int cidx = lane * 4;
    float4 gg = *reinterpret_cast<const float4*>(g + cidx);
    float4 bb = *reinterpret_cast<const float4*>(beta + cidx);
    float y0 = (v0 - mean) * inv * gg.x + bb.x;
    float y1 = (v1 - mean) * inv * gg.y + bb.y;
    float y2 = (v2 - mean) * inv * gg.z + bb.z;
    float y3 = (v3 - mean) * inv * gg.w + bb.w;
    y0 = y0 > 0.f ? y0 : 0.1f * y0;
    y1 = y1 > 0.f ? y1 : 0.1f * y1;
    y2 = y2 > 0.f ? y2 : 0.1f * y2;
    y3 = y3 > 0.f ? y3 : 0.1f * y3;
    *reinterpret_cast<float4*>(H + base) = make_float4(y0, y1, y2, y3);
}

// ---------------- final layer (D -> 1): warp-per-row GEMV --------------------
__global__ void final_gemv_kernel(const float* __restrict__ H,
                                  const float* __restrict__ W1, const float* __restrict__ b1,
                                  const float* __restrict__ W2,
                                  const float* __restrict__ W3, const float* __restrict__ b3,
                                  float* __restrict__ out, int N)
{
    int row = (blockIdx.x * blockDim.x + threadIdx.x) >> 5;
    int lane = threadIdx.x & 31;
    if (row >= N) return;
    size_t base = (size_t)row * D + lane * 4;
    float4 h = *reinterpret_cast<const float4*>(H + base);
    float4 w1 = *reinterpret_cast<const float4*>(W1 + lane * 4);
    float4 w2 = *reinterpret_cast<const float4*>(W2 + lane * 4);
    float4 w3 = *reinterpret_cast<const float4*>(W3 + lane * 4);
    float s1 = h.x * w1.x + h.y * w1.y + h.z * w1.z + h.w * w1.w;
    float s2 = h.x * w2.x + h.y * w2.y + h.z * w2.z + h.w * w2.w;
    float s3 = h.x * w3.x + h.y * w3.y + h.z * w3.z + h.w * w3.w;
#pragma unroll
    for (int o = 16; o; o >>= 1) {
        s1 += __shfl_xor_sync(0xFFFFFFFFu, s1, o);
        s2 += __shfl_xor_sync(0xFFFFFFFFu, s2, o);
        s3 += __shfl_xor_sync(0xFFFFFFFFu, s3, o);
    }
    if (lane == 0) {
        g_aO[row] = s1 + b1[0];
        out[row] = (s3 + b3[0]) - g_wsum[row] * s2;  // init: c - wsum*b
    }
}

__global__ void final_scatter_kernel(const int* __restrict__ src, const int* __restrict__ dst,
                                     const float* __restrict__ w, float* __restrict__ out, int E)
{
    int e = blockIdx.x * blockDim.x + threadIdx.x;
    if (e < E) atomicAdd(&out[dst[e]], w[e] * g_aO[src[e]]);
}

__global__ void sigmoid_kernel(float* __restrict__ out, int N) {
    int i = blockIdx.x * blockDim.x + threadIdx.x;
    if (i < N) out[i] = 1.f / (1.f + expf(-out[i]));
}

// ---------------- driver -----------------------------------------------------
extern "C" void kernel_launch(void* const* d_in, const int* in_sizes, int n_in,
                              void* d_out, int out_size)
{
    const float* x     = (const float*)d_in[0];
    const float* ew    = (const float*)d_in[1];
    const float* W1_in = (const float*)d_in[2];
    const float* b1_in = (const float*)d_in[3];
    const float* W2_in = (const float*)d_in[4];
    const float* W3_in = (const float*)d_in[5];
    const float* b3_in = (const float*)d_in[6];
    const float* W1_h  = (const float*)d_in[7];
    const float* b1_h  = (const float*)d_in[8];
    const float* W2_h  = (const float*)d_in[9];
    const float* W3_h  = (const float*)d_in[10];
    const float* b3_h  = (const float*)d_in[11];
    const float* W1_o  = (const float*)d_in[12];
    const float* b1_o  = (const float*)d_in[13];
    const float* W2_o  = (const float*)d_in[14];
    const float* W3_o  = (const float*)d_in[15];
    const float* b3_o  = (const float*)d_in[16];
    const float* g1    = (const float*)d_in[17];
    const float* be1   = (const float*)d_in[18];
    const float* g2    = (const float*)d_in[19];
    const float* be2   = (const float*)d_in[20];
    const int*   ei    = (const int*)d_in[21];

    int N = in_sizes[0] / D;
    int E = in_sizes[1];
    const int* src = ei;
    const int* dst = ei + E;
    float* out = (float*)d_out;

    float *H, *A, *B, *C, *AGG, *wsum, *colsum, *colsumsq;
    cudaGetSymbolAddress((void**)&H, g_H);
    cudaGetSymbolAddress((void**)&A, g_A);
    cudaGetSymbolAddress((void**)&B, g_B);
    cudaGetSymbolAddress((void**)&C, g_C);
    cudaGetSymbolAddress((void**)&AGG, g_AGG);
    cudaGetSymbolAddress((void**)&wsum, g_wsum);
    cudaGetSymbolAddress((void**)&colsum, g_colsum);
    cudaGetSymbolAddress((void**)&colsumsq, g_colsumsq);

    int n4 = N * (D / 4);

    // ---- input standardization ----
    zero_f<<<1, 128>>>(colsum, D);
    zero_f<<<1, 128>>>(colsumsq, D);
    colstats_kernel<<<296, 128>>>(x, N);
    colfinal_kernel<<<1, 128>>>(N);
    normalize_kernel<<<(n4 + 255) / 256, 256>>>((const float4*)x, (float4*)H, n4);

    // ---- wsum (layer-invariant) ----
    zero_f<<<(N + 255) / 256, 256>>>(wsum, N);
    wsum_kernel<<<(E + 255) / 256, 256>>>(dst, ew, E);

    // ---- 3 full LEConv layers ----
    struct LW { const float *W1, *b1, *W2, *W3, *b3, *g, *be; };
    LW layers[1 + NUM_INNER];
    layers[0] = {W1_in, b1_in, W2_in, W3_in, b3_in, g1, be1};
    for (int l = 1; l <= NUM_INNER; l++)
        layers[l] = {W1_h, b1_h, W2_h, W3_h, b3_h, g2, be2};

    int gemmGrid = (N + BM - 1) / BM;
    for (int l = 0; l < 1 + NUM_INNER; l++) {
        sgemm128<<<gemmGrid, 256>>>(H, layers[l].W1, layers[l].b1, A, N);
        sgemm128<<<gemmGrid, 256>>>(H, layers[l].W2, nullptr,      B, N);
        sgemm128<<<gemmGrid, 256>>>(H, layers[l].W3, layers[l].b3, C, N);
        zero_f4<<<(n4 + 255) / 256, 256>>>((float4*)AGG, n4);
        scatter_kernel<<<(E + 7) / 8, 256>>>(A, src, dst, ew, AGG, E);
        combine_ln_kernel<<<(N + 7) / 8, 256>>>(AGG, B, C, layers[l].g, layers[l].be, H, N);
    }

    // ---- output layer (D -> 1) + sigmoid ----
    final_gemv_kernel<<<(N + 7) / 8, 256>>>(H, W1_o, b1_o, W2_o, W3_o, b3_o, out, N);
    final_scatter_kernel<<<(E + 255) / 256, 256>>>(src, dst, ew, out, E);
    sigmoid_kernel<<<(N + 255) / 256, 256>>>(out, N);
}

// round 3
// speedup vs baseline: 1.2107x; 1.2107x over previous
#include <cuda_runtime.h>
#include <cuda_bf16.h>
#include <math.h>

// Problem constants (fixed by setup_inputs)
#define NMAX 50000
#define D 128
#define NUM_INNER 2   // number_of_layers = 4 -> 2 inner LEConv layers

// ---------------- scratch (device globals; no allocation allowed) -------------
__device__ float g_H[NMAX * D];     // activations (layer input)
__device__ float g_A[NMAX * D];     // lin1(x)+b1  -> gathered by edges
__device__ float g_AGG[NMAX * D];   // lin3(x)+b3 - wsum*lin2(x), then += edge scatter
__device__ float g_wsum[NMAX];      // sum of edge weights per dst
__device__ float g_aO[NMAX];        // final-layer lin1 scalar per node
__device__ float g_colsum[D];
__device__ float g_colsumsq[D];
__device__ float g_colmean[D];
__device__ float g_colinv[D];

// ---------------- utility kernels -------------------------------------------
__global__ void zero_f(float* p, int n) {
    int i = blockIdx.x * blockDim.x + threadIdx.x;
    if (i < n) p[i] = 0.f;
}

// per-column sum / sumsq over N rows (128 threads = 128 columns)
__global__ void colstats_kernel(const float* __restrict__ x, int N) {
    int c = threadIdx.x;
    float s = 0.f, ss = 0.f;
    for (int r = blockIdx.x; r < N; r += gridDim.x) {
        float v = x[(size_t)r * D + c];
        s += v;
        ss += v * v;
    }
    atomicAdd(&g_colsum[c], s);
    atomicAdd(&g_colsumsq[c], ss);
}

// finalize mean / 1/(std+1e-6) (std unbiased, ddof=1)
__global__ void colfinal_kernel(int N) {
    int c = threadIdx.x;
    float mean = g_colsum[c] / (float)N;
    float var = (g_colsumsq[c] - (float)N * mean * mean) / (float)(N - 1);
    var = fmaxf(var, 0.f);
    g_colmean[c] = mean;
    g_colinv[c] = 1.f / (sqrtf(var) + 1e-6f);
}

// x -> standardized H
__global__ void normalize_kernel(const float4* __restrict__ x4, float4* __restrict__ h4, int n4) {
    int i = blockIdx.x * blockDim.x + threadIdx.x;
    if (i >= n4) return;
    int c = (i & 31) * 4;
    float4 v = x4[i];
    v.x = (v.x - g_colmean[c + 0]) * g_colinv[c + 0];
    v.y = (v.y - g_colmean[c + 1]) * g_colinv[c + 1];
    v.z = (v.z - g_colmean[c + 2]) * g_colinv[c + 2];
    v.w = (v.w - g_colmean[c + 3]) * g_colinv[c + 3];
    h4[i] = v;
}

// wsum[dst] += w  (once; layer-invariant)
__global__ void wsum_kernel(const int* __restrict__ dst, const float* __restrict__ w, int E) {
    int e = blockIdx.x * blockDim.x + threadIdx.x;
    if (e < E) atomicAdd(&g_wsum[dst[e]], w[e]);
}

// ---------------- SGEMM: acc = X[M,128] @ W[128,128]; epilogue by MODE -------
// MODE 0: Out = acc + bias                     (A = lin1 + b1)
// MODE 1: Out = -wsum[row] * acc               (AGG init part 1: -ws*lin2)
// MODE 2: Out += acc + bias                    (AGG init part 2: += lin3 + b3)
#define BM 128
#define BN 128
#define BK 8
#define TM 8
#define TN 8

template<int MODE>
__global__ __launch_bounds__(256) void sgemm128(
    const float* __restrict__ X, const float* __restrict__ W,
    const float* __restrict__ bias, float* __restrict__ Out, int M)
{
    __shared__ float As[BK][BM];
    __shared__ float Bs[BK][BN];
    int tid = threadIdx.x;
    int tx = tid & 15;        // col group (0..15)
    int ty = tid >> 4;        // row group (0..15)
    int m0 = blockIdx.x * BM;

    int aRow = tid >> 1;            // 0..127
    int aK = (tid & 1) * 4;         // 0 or 4
    int bK = tid >> 5;              // 0..7
    int bN = (tid & 31) * 4;        // 0..124

    float acc[TM][TN];
#pragma unroll
    for (int i = 0; i < TM; i++)
#pragma unroll
        for (int j = 0; j < TN; j++) acc[i][j] = 0.f;

    for (int k0 = 0; k0 < D; k0 += BK) {
        float4 av = make_float4(0.f, 0.f, 0.f, 0.f);
        int gr = m0 + aRow;
        if (gr < M) av = *reinterpret_cast<const float4*>(X + (size_t)gr * D + k0 + aK);
        As[aK + 0][aRow] = av.x;
        As[aK + 1][aRow] = av.y;
        As[aK + 2][aRow] = av.z;
        As[aK + 3][aRow] = av.w;
        *reinterpret_cast<float4*>(&Bs[bK][bN]) =
            *reinterpret_cast<const float4*>(W + (size_t)(k0 + bK) * D + bN);
        __syncthreads();
#pragma unroll
        for (int k = 0; k < BK; k++) {
            float ra[TM], rb[TN];
            float4 a0 = *reinterpret_cast<const float4*>(&As[k][ty * TM]);
            float4 a1 = *reinterpret_cast<const float4*>(&As[k][ty * TM + 4]);
            ra[0] = a0.x; ra[1] = a0.y; ra[2] = a0.z; ra[3] = a0.w;
            ra[4] = a1.x; ra[5] = a1.y; ra[6] = a1.z; ra[7] = a1.w;
            float4 b0 = *reinterpret_cast<const float4*>(&Bs[k][tx * TN]);
            float4 b1 = *reinterpret_cast<const float4*>(&Bs[k][tx * TN + 4]);
            rb[0] = b0.x; rb[1] = b0.y; rb[2] = b0.z; rb[3] = b0.w;
            rb[4] = b1.x; rb[5] = b1.y; rb[6] = b1.z; rb[7] = b1.w;
#pragma unroll
            for (int i = 0; i < TM; i++)
#pragma unroll
                for (int j = 0; j < TN; j++) acc[i][j] = fmaf(ra[i], rb[j], acc[i][j]);
        }
        __syncthreads();
    }

#pragma unroll
    for (int i = 0; i < TM; i++) {
        int gm = m0 + ty * TM + i;
        if (gm >= M) continue;
        float ws = (MODE == 1) ? g_wsum[gm] : 0.f;
#pragma unroll
        for (int j = 0; j < TN; j += 4) {
            int gn = tx * TN + j;
            float4 v = make_float4(acc[i][j], acc[i][j + 1], acc[i][j + 2], acc[i][j + 3]);
            float* optr = Out + (size_t)gm * D + gn;
            if (MODE == 0 || MODE == 2) {
                v.x += bias[gn + 0];
                v.y += bias[gn + 1];
                v.z += bias[gn + 2];
                v.w += bias[gn + 3];
            }
            if (MODE == 1) {
                v.x *= -ws; v.y *= -ws; v.z *= -ws; v.w *= -ws;
            }
            if (MODE == 2) {
                float4 prev = *reinterpret_cast<const float4*>(optr);
                v.x += prev.x; v.y += prev.y; v.z += prev.z; v.w += prev.w;
            }
            *reinterpret_cast<float4*>(optr) = v;
        }
    }
}

// ---------------- edge scatter: AGG[dst] += w * A[src]  (warp per edge) ------
// red.global.add.v4.f32: one RED instruction per 16B instead of 4 scalar atomics.
__global__ __launch_bounds__(256) void scatter_kernel(
    const float* __restrict__ A, const int* __restrict__ src,
    const int* __restrict__ dst, const float* __restrict__ w,
    float* __restrict__ AGG, int E)
{
    int warpId = (blockIdx.x * blockDim.x + threadIdx.x) >> 5;
    int lane = threadIdx.x & 31;
    if (warpId >= E) return;
    int s = src[warpId];
    int d = dst[warpId];
    float wv = w[warpId];
    float4 v = *reinterpret_cast<const float4*>(A + (size_t)s * D + lane * 4);
    float* o = AGG + (size_t)d * D + lane * 4;
    asm volatile("red.global.add.v4.f32 [%0], {%1, %2, %3, %4};"
                 :: "l"(o), "f"(wv * v.x), "f"(wv * v.y), "f"(wv * v.z), "f"(wv * v.w)
                 : "memory");
}

// ---------------- LayerNorm + LeakyReLU (warp per row), AGG -> H -------------
__global__ void ln_kernel(const float* __restrict__ AGG, const float* __restrict__ g,
                          const float* __restrict__ beta, float* __restrict__ H, int N)
{
    int row = (blockIdx.x * blockDim.x + threadIdx.x) >> 5;
    int lane = threadIdx.x & 31;
    if (row >= N) return;
    size_t base = (size_t)row * D + lane * 4;
    float4 a = *reinterpret_cast<const float4*>(AGG + base);
    float v0 = a.x, v1 = a.y, v2 = a.z, v3 = a.w;
    float s = v0 + v1 + v2 + v3;
    float ss = v0 * v0 + v1 * v1 + v2 * v2 + v3 * v3;
#pragma unroll
    for (int o = 16; o; o >>= 1) {
        s += __shfl_xor_sync(0xFFFFFFFFu, s, o);
        ss += __shfl_xor_sync(0xFFFFFFFFu, ss, o);
    }
    float mean = s * (1.f / (float)D);
    float var = ss * (1.f / (float)D) - mean * mean;
    float inv = rsqrtf(var + 1e-5f);
    int cidx = lane * 4;
    float4 gg = *reinterpret_cast<const float4*>(g + cidx);
    float4 bb = *reinterpret_cast<const float4*>(beta + cidx);
    float y0 = (v0 - mean) * inv * gg.x + bb.x;
    float y1 = (v1 - mean) * inv * gg.y + bb.y;
    float y2 = (v2 - mean) * inv * gg.z + bb.z;
    float y3 = (v3 - mean) * inv * gg.w + bb.w;
    y0 = y0 > 0.f ? y0 : 0.1f * y0;
    y1 = y1 > 0.f ? y1 : 0.1f * y1;
    y2 = y2 > 0.f ? y2 : 0.1f * y2;
    y3 = y3 > 0.f ? y3 : 0.1f * y3;
    *reinterpret_cast<float4*>(H + base) = make_float4(y0, y1, y2, y3);
}

// ---------------- final layer (D -> 1): warp-per-row GEMV --------------------
__global__ void final_gemv_kernel(const float* __restrict__ H,
                                  const float* __restrict__ W1, const float* __restrict__ b1,
                                  const float* __restrict__ W2,
                                  const float* __restrict__ W3, const float* __restrict__ b3,
                                  float* __restrict__ out, int N)
{
    int row = (blockIdx.x * blockDim.x + threadIdx.x) >> 5;
    int lane = threadIdx.x & 31;
    if (row >= N) return;
    size_t base = (size_t)row * D + lane * 4;
    float4 h = *reinterpret_cast<const float4*>(H + base);
    float4 w1 = *reinterpret_cast<const float4*>(W1 + lane * 4);
    float4 w2 = *reinterpret_cast<const float4*>(W2 + lane * 4);
    float4 w3 = *reinterpret_cast<const float4*>(W3 + lane * 4);
    float s1 = h.x * w1.x + h.y * w1.y + h.z * w1.z + h.w * w1.w;
    float s2 = h.x * w2.x + h.y * w2.y + h.z * w2.z + h.w * w2.w;
    float s3 = h.x * w3.x + h.y * w3.y + h.z * w3.z + h.w * w3.w;
#pragma unroll
    for (int o = 16; o; o >>= 1) {
        s1 += __shfl_xor_sync(0xFFFFFFFFu, s1, o);
        s2 += __shfl_xor_sync(0xFFFFFFFFu, s2, o);
        s3 += __shfl_xor_sync(0xFFFFFFFFu, s3, o);
    }
    if (lane == 0) {
        g_aO[row] = s1 + b1[0];
        out[row] = (s3 + b3[0]) - g_wsum[row] * s2;  // init: c - wsum*b
    }
}

__global__ void final_scatter_kernel(const int* __restrict__ src, const int* __restrict__ dst,
                                     const float* __restrict__ w, float* __restrict__ out, int E)
{
    int e = blockIdx.x * blockDim.x + threadIdx.x;
    if (e < E) atomicAdd(&out[dst[e]], w[e] * g_aO[src[e]]);
}

__global__ void sigmoid_kernel(float* __restrict__ out, int N) {
    int i = blockIdx.x * blockDim.x + threadIdx.x;
    if (i < N) out[i] = 1.f / (1.f + expf(-out[i]));
}

// ---------------- driver -----------------------------------------------------
extern "C" void kernel_launch(void* const* d_in, const int* in_sizes, int n_in,
                              void* d_out, int out_size)
{
    const float* x     = (const float*)d_in[0];
    const float* ew    = (const float*)d_in[1];
    const float* W1_in = (const float*)d_in[2];
    const float* b1_in = (const float*)d_in[3];
    const float* W2_in = (const float*)d_in[4];
    const float* W3_in = (const float*)d_in[5];
    const float* b3_in = (const float*)d_in[6];
    const float* W1_h  = (const float*)d_in[7];
    const float* b1_h  = (const float*)d_in[8];
    const float* W2_h  = (const float*)d_in[9];
    const float* W3_h  = (const float*)d_in[10];
    const float* b3_h  = (const float*)d_in[11];
    const float* W1_o  = (const float*)d_in[12];
    const float* b1_o  = (const float*)d_in[13];
    const float* W2_o  = (const float*)d_in[14];
    const float* W3_o  = (const float*)d_in[15];
    const float* b3_o  = (const float*)d_in[16];
    const float* g1    = (const float*)d_in[17];
    const float* be1   = (const float*)d_in[18];
    const float* g2    = (const float*)d_in[19];
    const float* be2   = (const float*)d_in[20];
    const int*   ei    = (const int*)d_in[21];

    int N = in_sizes[0] / D;
    int E = in_sizes[1];
    const int* src = ei;
    const int* dst = ei + E;
    float* out = (float*)d_out;

    float *H, *A, *AGG, *wsum, *colsum, *colsumsq;
    cudaGetSymbolAddress((void**)&H, g_H);
    cudaGetSymbolAddress((void**)&A, g_A);
    cudaGetSymbolAddress((void**)&AGG, g_AGG);
    cudaGetSymbolAddress((void**)&wsum, g_wsum);
    cudaGetSymbolAddress((void**)&colsum, g_colsum);
    cudaGetSymbolAddress((void**)&colsumsq, g_colsumsq);

    int n4 = N * (D / 4);

    // ---- input standardization ----
    zero_f<<<1, 128>>>(colsum, D);
    zero_f<<<1, 128>>>(colsumsq, D);
    colstats_kernel<<<296, 128>>>(x, N);
    colfinal_kernel<<<1, 128>>>(N);
    normalize_kernel<<<(n4 + 255) / 256, 256>>>((const float4*)x, (float4*)H, n4);

    // ---- wsum (layer-invariant) ----
    zero_f<<<(N + 255) / 256, 256>>>(wsum, N);
    wsum_kernel<<<(E + 255) / 256, 256>>>(dst, ew, E);

    // ---- 3 full LEConv layers ----
    struct LW { const float *W1, *b1, *W2, *W3, *b3, *g, *be; };
    LW layers[1 + NUM_INNER];
    layers[0] = {W1_in, b1_in, W2_in, W3_in, b3_in, g1, be1};
    for (int l = 1; l <= NUM_INNER; l++)
        layers[l] = {W1_h, b1_h, W2_h, W3_h, b3_h, g2, be2};

    int gemmGrid = (N + BM - 1) / BM;
    for (int l = 0; l < 1 + NUM_INNER; l++) {
        sgemm128<0><<<gemmGrid, 256>>>(H, layers[l].W1, layers[l].b1, A, N);   // A = lin1+b1
        sgemm128<1><<<gemmGrid, 256>>>(H, layers[l].W2, nullptr,      AGG, N); // AGG = -ws*lin2
        sgemm128<2><<<gemmGrid, 256>>>(H, layers[l].W3, layers[l].b3, AGG, N); // AGG += lin3+b3
        scatter_kernel<<<(E + 7) / 8, 256>>>(A, src, dst, ew, AGG, E);         // AGG += w*A[src]
        ln_kernel<<<(N + 7) / 8, 256>>>(AGG, layers[l].g, layers[l].be, H, N);
    }

    // ---- output layer (D -> 1) + sigmoid ----
    final_gemv_kernel<<<(N + 7) / 8, 256>>>(H, W1_o, b1_o, W2_o, W3_o, b3_o, out, N);
    final_scatter_kernel<<<(E + 255) / 256, 256>>>(src, dst, ew, out, E);
    sigmoid_kernel<<<(N + 255) / 256, 256>>>(out, N);
}